// round 14
// baseline (speedup 1.0000x reference)
#include <cuda_runtime.h>
#include <math.h>

#define Nn 1024
#define Cc 1000
#define Aa 64
#define SP 1024      /* padded S (distinct classes) */
#define RP 2112      /* padded rows */
#define CP 1024      /* padded C for row stride */
#define KS 2         /* K-split for quad phase / cross halves */
#define KSF 4        /* K-split for F build */

static __device__ int   g_counts[Cc];
static __device__ int   g_coff[Cc];
static __device__ int   g_slot[Cc];
static __device__ int   g_kidx[SP];
static __device__ int   g_list[Nn];
static __device__ float g_wCV[Cc];
static __device__ int   g_Svar;
static __device__ int   g_Rvar;
static __device__ int   g_Jvar;
static __device__ int   g_rowbase[Cc];
static __device__ int   g_j2cls[SP];
static __device__ int   g_j2row0[SP];
static __device__ int   g_j2len[SP];
static __device__ int   g_rcls[RP];
static __device__ float g_racoef[RP];
static __device__ float g_X[RP*Aa];
static __device__ float g_P[RP*CP];
static __device__ float g_kgT[Cc*SP];     /* kgT[j][s] = delta or kg[kidx[s]][j] */
static __device__ float g_E[RP*SP];
static __device__ float g_G[SP*CP];       /* G[j][c] = sum_{r in class-run j} ac*P^2 */
static __device__ float g_Fp[KSF*Aa*SP];  /* partial F, transposed: [z][a][s] */
static __device__ float g_quad[KS*SP*CP];
static __device__ float g_crossX[KS*SP*CP];
static __device__ float g_quadCS[SP*CP];  /* cov_state fallback terms (valid iff csflag) */
static __device__ float g_crossCS[SP*CP];
static __device__ float g_nllw[Nn];
static __device__ float g_wn[Nn];
static __device__ int   g_csflag;
static __device__ unsigned g_done = 0;

// packed f32x2 helpers (sm_100+ PTX)
__device__ __forceinline__ unsigned long long pack2(float lo, float hi) {
    unsigned long long d;
    asm("mov.b64 %0, {%1, %2};" : "=l"(d) : "f"(lo), "f"(hi));
    return d;
}
__device__ __forceinline__ void fma2(unsigned long long& acc, unsigned long long a, unsigned long long b) {
    asm("fma.rn.f32x2 %0, %1, %2, %0;" : "+l"(acc) : "l"(a), "l"(b));
}

// dual inclusive scan of 1024 (v1,v2) pairs via warp shuffles
__device__ __forceinline__ void scan2_1024(int& v1, int& v2, int lane, int w,
                                           int* wsum1, int* wsum2) {
    #pragma unroll
    for (int o = 1; o < 32; o <<= 1) {
        int x1 = __shfl_up_sync(0xffffffffu, v1, o);
        int x2 = __shfl_up_sync(0xffffffffu, v2, o);
        if (lane >= o) { v1 += x1; v2 += x2; }
    }
    if (lane == 31) { wsum1[w] = v1; wsum2[w] = v2; }
    __syncthreads();
    if (w == 0) {
        int s1 = wsum1[lane], s2 = wsum2[lane];
        #pragma unroll
        for (int o = 1; o < 32; o <<= 1) {
            int x1 = __shfl_up_sync(0xffffffffu, s1, o);
            int x2 = __shfl_up_sync(0xffffffffu, s2, o);
            if (lane >= o) { s1 += x1; s2 += x2; }
        }
        wsum1[lane] = s1; wsum2[lane] = s2;
    }
    __syncthreads();
    if (w > 0) { v1 += wsum1[w-1]; v2 += wsum2[w-1]; }
}

// ---------------- fused stats, 1 block ----------------
__global__ void __launch_bounds__(1024) k_stats(const int* __restrict__ labels,
                                                const float* __restrict__ amount) {
    __shared__ int   lab[1024];
    __shared__ int   scnt[1024];
    __shared__ int   scoff[1024];
    __shared__ int   wsum1[32], wsum2[32];
    int t = threadIdx.x, lane = t & 31, w = t >> 5;
    scnt[t] = 0;
    lab[t] = labels[t];
    if (t == 0) g_csflag = 0;
    __syncthreads();
    int l = lab[t];
    unsigned peers = __match_any_sync(0xffffffffu, l);
    int rin  = __popc(peers & ((1u << lane) - 1u));
    int ldr  = __ffs(peers) - 1;
    int cntw = __popc(peers);
    int base = 0;
    for (int ww = 0; ww < 32; ww++) {   // deterministic within-class ordering
        if (w == ww) {
            int old = 0;
            if (lane == ldr) old = atomicAdd(&scnt[l], cntw);
            base = __shfl_sync(0xffffffffu, old, ldr);
        }
        __syncthreads();
    }
    int myrank = base + rin;
    int cnt  = (t < Cc) ? scnt[t] : 0;
    int flag = (cnt > 0) ? 1 : 0;
    int v1 = cnt, v2 = flag;
    scan2_1024(v1, v2, lane, w, wsum1, wsum2);
    float wv = 0.f;
    if (t < Cc) {
        int coff = v1 - cnt;
        scoff[t] = coff;
        g_coff[t] = coff;
        g_counts[t] = cnt;
        int slot = v2 - flag;
        g_slot[t] = flag ? slot : -1;
        if (flag) g_kidx[slot] = t;
        float cf = (float)cnt;
        float denom = cf + amount[t];
        wv = (denom > 0.f) ? (cf / denom) : 0.f;
        g_wCV[t] = wv;
    }
    if (t == 0) g_Svar = wsum2[31];
    __syncthreads();
    g_list[scoff[l] + myrank] = t;
    // class-grouped row runs
    int rl = 0;
    if (t < Cc) {
        float coef2 = wv*(1.f - wv);
        rl = ((cnt >= 2) ? cnt : 0) + ((coef2 != 0.f) ? 1 : 0);
    }
    int f2 = (rl > 0) ? 1 : 0;
    __syncthreads();
    int v3 = rl, v4 = f2;
    scan2_1024(v3, v4, lane, w, wsum1, wsum2);
    if (t < Cc) {
        int rb = v3 - rl;
        g_rowbase[t] = rb;
        if (f2) {
            int j = v4 - f2;
            g_j2cls[j] = t;
            g_j2row0[j] = rb;
            g_j2len[j] = rl;
        }
    }
    if (t == 0) { g_Rvar = wsum1[31]; g_Jvar = wsum2[31]; }
}

// ---------------- fused per-class mean + centered-row fill (class-grouped slots) ----
__global__ void k_avefill(const float* __restrict__ f,
                          const float* __restrict__ ave_state) {
    int c = blockIdx.x, a = threadIdx.x;
    int cnt = g_counts[c], off = g_coff[c];
    float acc = 0.f;
    for (int i = 0; i < cnt; i++) acc += f[g_list[off+i]*Aa + a];
    float ave = acc / (float)(cnt > 0 ? cnt : 1);
    float w = g_wCV[c];
    int base = g_rowbase[c];
    bool sact = (cnt >= 2);
    if (sact) {
        float ac = w / (float)cnt;
        for (int i = 0; i < cnt; i++) {
            int n = g_list[off+i];
            int s = base + i;
            g_X[s*Aa + a] = f[n*Aa + a] - ave;
            if (a == 0) { g_rcls[s] = c; g_racoef[s] = ac; }
        }
    }
    float coef2 = w*(1.f - w);
    if (coef2 != 0.f) {
        int s2 = base + (sact ? cnt : 0);
        g_X[s2*Aa + a] = ave_state[c*Aa + a] - ave;
        if (a == 0) { g_rcls[s2] = c; g_racoef[s2] = coef2; }
    }
}

// P = X.W^T (64x64 tiles). Spare blocks: cov_state zero-scan + kgT transpose build.
__global__ void __launch_bounds__(256) k_P(const float* __restrict__ W,
                                           const float* __restrict__ cov,
                                           const float* __restrict__ kg,
                                           const int* __restrict__ headp) {
    int R = g_Rvar;
    int nkr64 = (R + 63) & ~63;
    int nby = nkr64 >> 6;
    int by = blockIdx.y, bx = blockIdx.x;
    __shared__ float Xs[64][65];
    __shared__ float Ws[64][65];
    int t = threadIdx.x;
    if (by >= nby) {
        int spare  = (by - nby)*gridDim.x + bx;
        int nspare = (gridDim.y - nby)*gridDim.x;
        {   // 1) cov_state zero-scan
            const float4* c4 = (const float4*)cov;
            int total = Cc*Aa*Aa/4;
            int found = 0;
            for (int i = spare*256 + t; i < total; i += nspare*256) {
                float4 v = c4[i];
                found |= (v.x != 0.f) | (v.y != 0.f) | (v.z != 0.f) | (v.w != 0.f);
            }
            if (found) atomicOr(&g_csflag, 1);
        }
        {   // 2) kgT build
            int S = g_Svar, hd = headp[0];
            float* tile = &Xs[0][0];            // reuse smem: 32x33 tile
            int tx = t & 31, ty8 = t >> 5;
            for (int tid = spare; tid < 1024; tid += nspare) {
                int s0 = (tid & 31) * 32;
                int j0 = (tid >> 5) * 32;
                #pragma unroll
                for (int i = 0; i < 4; i++) {
                    int row = ty8 + 8*i;
                    int s = s0 + row, j = j0 + tx;
                    float v = 0.f;
                    if (s < S && j < Cc) {
                        int k = g_kidx[s];
                        v = (k < hd) ? ((j == k) ? 1.f : 0.f) : kg[k*Cc + j];
                    }
                    tile[row*33 + tx] = v;
                }
                __syncthreads();
                #pragma unroll
                for (int i = 0; i < 4; i++) {
                    int row = ty8 + 8*i;
                    int j = j0 + row;
                    if (j < Cc) g_kgT[j*SP + s0 + tx] = tile[tx*33 + row];
                }
                __syncthreads();
            }
        }
        return;
    }
    int r0 = by*64, c0 = bx*64;
    for (int i = t; i < 64*64; i += 256) {
        int rr = i >> 6, kk = i & 63;
        int r = r0 + rr;
        Xs[rr][kk] = (r < R) ? g_X[r*Aa + kk] : 0.f;
        int c = c0 + rr;
        Ws[rr][kk] = (c < Cc) ? W[c*Aa + kk] : 0.f;
    }
    __syncthreads();
    int tx = t & 15, ty = t >> 4;
    float acc[4][4] = {};
    #pragma unroll 4
    for (int k = 0; k < 64; k++) {
        float xv[4], wv[4];
        #pragma unroll
        for (int i = 0; i < 4; i++) xv[i] = Xs[ty*4+i][k];
        #pragma unroll
        for (int j = 0; j < 4; j++) wv[j] = Ws[tx*4+j][k];
        #pragma unroll
        for (int i = 0; i < 4; i++)
            #pragma unroll
            for (int j = 0; j < 4; j++)
                acc[i][j] += xv[i]*wv[j];
    }
    #pragma unroll
    for (int i = 0; i < 4; i++) {
        int r = r0 + ty*4 + i;
        float4 v = (r < R) ? make_float4(acc[i][0], acc[i][1], acc[i][2], acc[i][3])
                           : make_float4(0.f, 0.f, 0.f, 0.f);
        *(float4*)&g_P[r*CP + c0 + tx*4] = v;
    }
}

// E[r,s] = beta*ac[r]*kgT[cl[r]][s]*P[r,kidx[s]]  (s < Smax64 only; pad rows 0)
// Spare y-blocks build G[j,c] = sum_{r in run j} ac*P[r,c]^2
__global__ void __launch_bounds__(256) k_BE(const float* __restrict__ betap) {
    int R = g_Rvar;
    int nkr = (R + 15) & ~15;
    int nbyUsed = (nkr + 3) >> 2;
    int by = blockIdx.y;
    int t = threadIdx.x;
    if (by >= nbyUsed) {
        // ---- spare blocks: build G rows ----
        int spare  = (by - nbyUsed)*gridDim.x + blockIdx.x;
        int nspare = (gridDim.y - nbyUsed)*gridDim.x;
        int J = g_Jvar;
        int JP = (J + 15) & ~15;
        for (int j = spare; j < JP; j += nspare) {
            if (j < J) {
                int row0 = g_j2row0[j], len = g_j2len[j];
                for (int c = t*4; c < CP; c += 1024) {
                    float4 acc = make_float4(0.f, 0.f, 0.f, 0.f);
                    for (int i = 0; i < len; i++) {
                        int r = row0 + i;
                        float ac = g_racoef[r];
                        float4 p = *(const float4*)&g_P[r*CP + c];
                        acc.x += ac*p.x*p.x; acc.y += ac*p.y*p.y;
                        acc.z += ac*p.z*p.z; acc.w += ac*p.w*p.w;
                    }
                    *(float4*)&g_G[j*CP + c] = acc;
                }
            } else {
                for (int c = t*4; c < CP; c += 1024)
                    *(float4*)&g_G[j*CP + c] = make_float4(0.f, 0.f, 0.f, 0.f);
            }
        }
        return;
    }
    int S = g_Svar;
    int Smax64 = (S + 63) & ~63;
    if ((int)(blockIdx.x*256) >= Smax64) return;   // dead E columns
    int rbase = by*4;
    int s = blockIdx.x*256 + t;
    bool sv = (s < S);
    int k = sv ? g_kidx[s] : 0;
    float beta = betap[0];
    int   cl[4]; float ac[4];
    #pragma unroll
    for (int i = 0; i < 4; i++) {
        int r = rbase + i;
        cl[i] = (r < R) ? g_rcls[r] : 0;
        ac[i] = (r < R) ? g_racoef[r] : 0.f;
    }
    float kv[4], pv[4];
    #pragma unroll
    for (int i = 0; i < 4; i++) kv[i] = sv ? g_kgT[cl[i]*SP + s] : 0.f;
    #pragma unroll
    for (int i = 0; i < 4; i++) {
        int r = rbase + i;
        pv[i] = (sv && r < R) ? g_P[r*CP + k] : 0.f;
    }
    #pragma unroll
    for (int i = 0; i < 4; i++) {
        int r = rbase + i;
        float e = (sv && r < R) ? beta * ac[i] * kv[i] * pv[i] : 0.f;
        g_E[r*SP + s] = e;
    }
}

// F_partial[z] = (E^T X) K-chunk; z==0 also folds -alpha*out_new[k_s,:].
// Stored transposed: g_Fp[z][a][s].
__global__ void __launch_bounds__(256) k_F(const float* __restrict__ out_new,
                                           const float* __restrict__ alphap) {
    int s0 = blockIdx.x*64;
    if (s0 >= ((g_Svar + 63) & ~63)) return;       // dead s tiles
    int z = blockIdx.y;
    int t = threadIdx.x;
    int tx = t & 15, ty = t >> 4;
    int lr = t >> 4, lc = (t & 15)*4;
    int R = g_Rvar;
    int nkr = (R + 15) & ~15;
    int nt = nkr >> 4;
    int per = (nt + KSF - 1)/KSF;
    int ta = z*per, tb = ta + per; if (tb > nt) tb = nt;
    __shared__ __align__(16) float Es[16][64];
    __shared__ __align__(16) float Xs[16][64];
    float acc[4][4] = {};
    for (int tt = ta; tt < tb; tt++) {
        int r = tt*16 + lr;
        *(float4*)&Es[lr][lc] = *(const float4*)&g_E[r*SP + s0 + lc];
        *(float4*)&Xs[lr][lc] = *(const float4*)&g_X[r*Aa + lc];
        __syncthreads();
        #pragma unroll
        for (int u = 0; u < 16; u++) {
            float ev[4], xv[4];
            #pragma unroll
            for (int i = 0; i < 4; i++) ev[i] = Es[u][ty*4+i];
            #pragma unroll
            for (int j = 0; j < 4; j++) xv[j] = Xs[u][tx*4+j];
            #pragma unroll
            for (int i = 0; i < 4; i++)
                #pragma unroll
                for (int j = 0; j < 4; j++)
                    acc[i][j] += ev[i]*xv[j];
        }
        __syncthreads();
    }
    if (z == 0) {
        float alpha = alphap[0];
        #pragma unroll
        for (int i = 0; i < 4; i++) {
            int s = s0 + ty*4 + i;
            int k = (s < g_Svar) ? g_kidx[s] : 0;
            #pragma unroll
            for (int j = 0; j < 4; j++)
                acc[i][j] -= alpha * out_new[k*Aa + tx*4 + j];
        }
    }
    #pragma unroll
    for (int i = 0; i < 4; i++)
        #pragma unroll
        for (int j = 0; j < 4; j++)
            g_Fp[z*Aa*SP + (tx*4+j)*SP + (s0 + ty*4 + i)] = acc[i][j];
}

// k_QC: z<2: quad = kgT_grouped^T G (split) + crossX_half = F * W^T over a-range [z*32, z*32+32)
//       z==2: guarded cov_state fallback -> CS buffers (no-op when csflag==0)
__global__ void __launch_bounds__(256) k_QC(const float* __restrict__ W,
                                            const float* __restrict__ cov,
                                            const float* __restrict__ kg,
                                            const float* __restrict__ betap,
                                            const int* __restrict__ headp) {
    int z = blockIdx.z;
    int t = threadIdx.x;
    __shared__ __align__(16) float As[16][64];
    __shared__ __align__(16) float Ms[16][64];
    if (z == 2) {
        if (!g_csflag) return;
        __shared__ float M[Aa*Aa];
        int sidx = blockIdx.y*16 + blockIdx.x;   // 0..255
        int S = g_Svar, hd = headp[0];
        float beta = betap[0];
        for (int m = 0; m < 4; m++) {
            int s = sidx + 256*m;
            if (s >= S) continue;
            int k = g_kidx[s];
            for (int idx = t; idx < Aa*Aa; idx += 256) {
                float v;
                if (k < hd) v = (1.f - g_wCV[k]) * cov[k*4096 + idx];
                else {
                    v = 0.f;
                    for (int j = 0; j < Cc; j++)
                        v += kg[k*Cc + j] * (1.f - g_wCV[j]) * cov[j*4096 + idx];
                }
                M[idx] = v;
            }
            __syncthreads();
            for (int c = t; c < Cc; c += 256) {
                float q = 0.f, cr = 0.f, cr2 = 0.f;
                for (int a = 0; a < Aa; a++) {
                    float ta2 = 0.f, ua = 0.f;
                    for (int b2 = 0; b2 < Aa; b2++) {
                        ta2 += M[a*Aa + b2] * W[c*Aa + b2];
                        ua  += M[a*Aa + b2] * W[k*Aa + b2];
                    }
                    q   += W[c*Aa + a] * ta2;
                    cr  += W[k*Aa + a] * ta2;
                    cr2 += W[c*Aa + a] * ua;
                }
                g_quadCS[s*CP + c]  = q;
                g_crossCS[s*CP + c] = beta * 0.5f * (cr + cr2);
            }
            __syncthreads();
        }
        return;
    }
    int s0 = blockIdx.y*64;
    if (s0 >= g_Svar) return;
    int c0 = blockIdx.x*64;
    int tx = t & 15, ty = t >> 4;
    int lr = t >> 4, lc = (t & 15)*4;
    unsigned long long qacc[8];
    #pragma unroll
    for (int i = 0; i < 8; i++) qacc[i] = 0ULL;
    // ---- quad phase (K split over z<2) ----
    {
        int J = g_Jvar;
        int JP = (J + 15) & ~15;
        int nt = JP >> 4;
        int per = (nt + KS - 1)/KS;
        int ta = z*per, tb = ta + per; if (tb > nt) tb = nt;
        if (ta < tb) {
            float4 rA, rM;
            {
                int j = ta*16 + lr;
                rA = (j < J) ? *(const float4*)&g_kgT[g_j2cls[j]*SP + s0 + lc]
                             : make_float4(0.f,0.f,0.f,0.f);
                rM = *(const float4*)&g_G[j*CP + c0 + lc];
            }
            for (int tt = ta; tt < tb; tt++) {
                *(float4*)&As[lr][lc] = rA;
                *(float4*)&Ms[lr][lc] = rM;
                __syncthreads();
                if (tt + 1 < tb) {
                    int j = (tt+1)*16 + lr;
                    rA = (j < J) ? *(const float4*)&g_kgT[g_j2cls[j]*SP + s0 + lc]
                                 : make_float4(0.f,0.f,0.f,0.f);
                    rM = *(const float4*)&g_G[j*CP + c0 + lc];
                }
                #pragma unroll
                for (int u = 0; u < 16; u++) {
                    float4 kv = *(float4*)&As[u][ty*4];
                    ulonglong2 gv = *(ulonglong2*)&Ms[u][tx*4];
                    unsigned long long k2[4];
                    k2[0] = pack2(kv.x, kv.x); k2[1] = pack2(kv.y, kv.y);
                    k2[2] = pack2(kv.z, kv.z); k2[3] = pack2(kv.w, kv.w);
                    #pragma unroll
                    for (int i = 0; i < 4; i++) {
                        fma2(qacc[i*2+0], k2[i], gv.x);
                        fma2(qacc[i*2+1], k2[i], gv.y);
                    }
                }
                __syncthreads();
            }
        }
    }
    int zoff = z*SP*CP;
    #pragma unroll
    for (int i = 0; i < 4; i++) {
        int s = s0 + ty*4 + i;
        unsigned long long* q = (unsigned long long*)&g_quad[zoff + s*CP + c0 + tx*4];
        q[0] = qacc[i*2+0]; q[1] = qacc[i*2+1];
    }
    // ---- cross half: a in [z*32, z*32+32) ----
    __shared__ float Wt[64][17];
    __syncthreads();
    float acc[4][4] = {};
    for (int a0 = z*32; a0 < z*32 + 32; a0 += 16) {
        {
            int a = a0 + lr;
            float4 v = make_float4(0.f, 0.f, 0.f, 0.f);
            #pragma unroll
            for (int zz = 0; zz < KSF; zz++) {
                float4 f = *(const float4*)&g_Fp[zz*Aa*SP + a*SP + s0 + lc];
                v.x += f.x; v.y += f.y; v.z += f.z; v.w += f.w;
            }
            *(float4*)&As[lr][lc] = v;       // As[a_local][s_local]
        }
        {
            int cl = t >> 2;
            int aw = (t & 3)*4;
            int c = c0 + cl;
            float4 wv = (c < Cc) ? *(const float4*)&W[c*Aa + a0 + aw]
                                 : make_float4(0.f,0.f,0.f,0.f);
            Wt[cl][aw+0] = wv.x; Wt[cl][aw+1] = wv.y;
            Wt[cl][aw+2] = wv.z; Wt[cl][aw+3] = wv.w;
        }
        __syncthreads();
        #pragma unroll
        for (int u = 0; u < 16; u++) {
            float fv[4], wv2[4];
            #pragma unroll
            for (int i = 0; i < 4; i++) fv[i] = As[u][ty*4+i];
            #pragma unroll
            for (int j = 0; j < 4; j++) wv2[j] = Wt[tx*4+j][u % 16];
            #pragma unroll
            for (int i = 0; i < 4; i++)
                #pragma unroll
                for (int j = 0; j < 4; j++)
                    acc[i][j] += fv[i]*wv2[j];
        }
        __syncthreads();
    }
    #pragma unroll
    for (int i = 0; i < 4; i++) {
        int s = s0 + ty*4 + i;
        *(float4*)&g_crossX[zoff + s*CP + c0 + tx*4] =
            make_float4(acc[i][0], acc[i][1], acc[i][2], acc[i][3]);
    }
}

// ---- weighted CE (2 quad + 2 cross halves [+ CS if flagged]) + fused final ----
__global__ void __launch_bounds__(256) k_ce(const float* __restrict__ y_s,
                     const float* __restrict__ weights,
                     const int* __restrict__ labels,
                     const float* __restrict__ betap,
                     float* __restrict__ out) {
    int n = blockIdx.x, t = threadIdx.x;
    int k = labels[n];
    int s = g_slot[k];
    int csf = g_csflag;
    float hb = 0.5f * betap[0];
    __shared__ float red[256];
    __shared__ float sLk;
    __shared__ int slast;
    float L[4];
    float mx = -3.4e38f;
    #pragma unroll
    for (int i = 0; i < 4; i++) {
        int c = t + i*256;
        float v = -3.4e38f;
        if (c < Cc) {
            float q = g_quad[s*CP + c] + g_quad[SP*CP + s*CP + c];
            float x = g_crossX[s*CP + c] + g_crossX[SP*CP + s*CP + c];
            if (csf) { q += g_quadCS[s*CP + c]; x += g_crossCS[s*CP + c]; }
            v = y_s[n*Cc + c] + hb*q - x;
            if (c == k) sLk = v;
        }
        L[i] = v;
        mx = fmaxf(mx, v);
    }
    red[t] = mx; __syncthreads();
    for (int o = 128; o > 0; o >>= 1) {
        if (t < o) red[t] = fmaxf(red[t], red[t+o]);
        __syncthreads();
    }
    float m = red[0]; __syncthreads();
    float se = 0.f;
    #pragma unroll
    for (int i = 0; i < 4; i++) {
        int c = t + i*256;
        if (c < Cc) se += expf(L[i] - m);
    }
    red[t] = se; __syncthreads();
    for (int o = 128; o > 0; o >>= 1) {
        if (t < o) red[t] += red[t+o];
        __syncthreads();
    }
    if (t == 0) {
        float lse = m + logf(red[0]);
        float w = weights[k];
        g_nllw[n] = w * (lse - sLk);
        g_wn[n] = w;
        __threadfence();
        unsigned v = atomicAdd(&g_done, 1u);
        slast = (v == (unsigned)(gridDim.x - 1)) ? 1 : 0;
    }
    __syncthreads();
    if (slast) {
        if (t == 0) { g_done = 0; __threadfence(); }
        __syncthreads();
        float a = g_nllw[t] + g_nllw[t+256] + g_nllw[t+512] + g_nllw[t+768];
        float b = g_wn[t]   + g_wn[t+256]   + g_wn[t+512]   + g_wn[t+768];
        red[t] = a; __syncthreads();
        for (int o = 128; o > 0; o >>= 1) {
            if (t < o) red[t] += red[t+o];
            __syncthreads();
        }
        a = red[0]; __syncthreads();
        red[t] = b; __syncthreads();
        for (int o = 128; o > 0; o >>= 1) {
            if (t < o) red[t] += red[t+o];
            __syncthreads();
        }
        if (t == 0) out[0] = a / red[0];
    }
}

extern "C" void kernel_launch(void* const* d_in, const int* in_sizes, int n_in,
                              void* d_out, int out_size) {
    const float* features  = (const float*)d_in[0];
    const float* y_s       = (const float*)d_in[1];
    const float* weights   = (const float*)d_in[2];
    const float* kg        = (const float*)d_in[3];
    const float* out_new   = (const float*)d_in[4];
    const float* fc_weight = (const float*)d_in[5];
    const float* alpha     = (const float*)d_in[6];
    const float* beta      = (const float*)d_in[7];
    const float* cov_state = (const float*)d_in[8];
    const float* ave_state = (const float*)d_in[9];
    const float* amount    = (const float*)d_in[10];
    const int*   labels    = (const int*)d_in[11];
    const int*   headp     = (const int*)d_in[12];
    float* out = (float*)d_out;

    k_stats<<<1, 1024>>>(labels, amount);
    k_avefill<<<Cc, Aa>>>(features, ave_state);
    {
        dim3 g(CP/64, RP/64 + 1);   // spare blocks: cov scan + kgT build
        k_P<<<g, 256>>>(fc_weight, cov_state, kg, headp);
    }
    {
        dim3 g(SP/256, RP/4);       // spare blocks: G build
        k_BE<<<g, 256>>>(beta);
    }
    {
        dim3 g(SP/64, KSF);
        k_F<<<g, 256>>>(out_new, alpha);
    }
    {
        dim3 g(CP/64, SP/64, 3);    // z=0,1: quad split + cross halves; z=2: cs fallback
        k_QC<<<g, 256>>>(fc_weight, cov_state, kg, beta, headp);
    }
    k_ce<<<Nn, 256>>>(y_s, weights, labels, beta, out);
}

// round 15
// speedup vs baseline: 1.2841x; 1.2841x over previous
#include <cuda_runtime.h>
#include <math.h>

#define Nn 1024
#define Cc 1000
#define Aa 64
#define SP 1024      /* padded S (distinct classes) */
#define RP 2112      /* padded rows */
#define CP 1024      /* padded C for row stride */
#define KS 2         /* K-split for quad phase */
#define KSF 4        /* K-split for F build */

static __device__ int   g_counts[Cc];
static __device__ int   g_coff[Cc];
static __device__ int   g_slot[Cc];
static __device__ int   g_kidx[SP];
static __device__ int   g_list[Nn];
static __device__ float g_wCV[Cc];
static __device__ int   g_Svar;
static __device__ int   g_Rvar;
static __device__ int   g_Jvar;
static __device__ int   g_rowbase[Cc];
static __device__ int   g_j2cls[SP];
static __device__ int   g_j2row0[SP];
static __device__ int   g_j2len[SP];
static __device__ int   g_rcls[RP];
static __device__ float g_racoef[RP];
static __device__ float g_X[RP*Aa];
static __device__ float g_P[RP*CP];
static __device__ float g_kgT[Cc*SP];     /* kgT[j][s] = delta or kg[kidx[s]][j] */
static __device__ float g_E[RP*SP];
static __device__ float g_G[SP*CP];       /* G[j][c] = sum_{r in class-run j} ac*P^2 */
static __device__ float g_Fp[KSF*Aa*SP];  /* partial F, transposed: [z][a][s] */
static __device__ float g_quad[KS*SP*CP];
static __device__ float g_crossX[SP*CP];
static __device__ float g_nllw[Nn];
static __device__ float g_wn[Nn];
static __device__ int   g_csflag;
static __device__ unsigned g_done = 0;

// packed f32x2 helpers (sm_100+ PTX)
__device__ __forceinline__ unsigned long long pack2(float lo, float hi) {
    unsigned long long d;
    asm("mov.b64 %0, {%1, %2};" : "=l"(d) : "f"(lo), "f"(hi));
    return d;
}
__device__ __forceinline__ void fma2(unsigned long long& acc, unsigned long long a, unsigned long long b) {
    asm("fma.rn.f32x2 %0, %1, %2, %0;" : "+l"(acc) : "l"(a), "l"(b));
}

// dual inclusive scan of 1024 (v1,v2) pairs via warp shuffles
__device__ __forceinline__ void scan2_1024(int& v1, int& v2, int lane, int w,
                                           int* wsum1, int* wsum2) {
    #pragma unroll
    for (int o = 1; o < 32; o <<= 1) {
        int x1 = __shfl_up_sync(0xffffffffu, v1, o);
        int x2 = __shfl_up_sync(0xffffffffu, v2, o);
        if (lane >= o) { v1 += x1; v2 += x2; }
    }
    if (lane == 31) { wsum1[w] = v1; wsum2[w] = v2; }
    __syncthreads();
    if (w == 0) {
        int s1 = wsum1[lane], s2 = wsum2[lane];
        #pragma unroll
        for (int o = 1; o < 32; o <<= 1) {
            int x1 = __shfl_up_sync(0xffffffffu, s1, o);
            int x2 = __shfl_up_sync(0xffffffffu, s2, o);
            if (lane >= o) { s1 += x1; s2 += x2; }
        }
        wsum1[lane] = s1; wsum2[lane] = s2;
    }
    __syncthreads();
    if (w > 0) { v1 += wsum1[w-1]; v2 += wsum2[w-1]; }
}

// ---------------- fused stats, 1 block ----------------
__global__ void __launch_bounds__(1024) k_stats(const int* __restrict__ labels,
                                                const float* __restrict__ amount) {
    __shared__ int   lab[1024];
    __shared__ int   scnt[1024];
    __shared__ int   scoff[1024];
    __shared__ int   wsum1[32], wsum2[32];
    int t = threadIdx.x, lane = t & 31, w = t >> 5;
    scnt[t] = 0;
    lab[t] = labels[t];
    if (t == 0) g_csflag = 0;
    __syncthreads();
    int l = lab[t];
    unsigned peers = __match_any_sync(0xffffffffu, l);
    int rin  = __popc(peers & ((1u << lane) - 1u));
    int ldr  = __ffs(peers) - 1;
    int cntw = __popc(peers);
    int base = 0;
    for (int ww = 0; ww < 32; ww++) {   // deterministic within-class ordering
        if (w == ww) {
            int old = 0;
            if (lane == ldr) old = atomicAdd(&scnt[l], cntw);
            base = __shfl_sync(0xffffffffu, old, ldr);
        }
        __syncthreads();
    }
    int myrank = base + rin;
    int cnt  = (t < Cc) ? scnt[t] : 0;
    int flag = (cnt > 0) ? 1 : 0;
    int v1 = cnt, v2 = flag;
    scan2_1024(v1, v2, lane, w, wsum1, wsum2);
    float wv = 0.f;
    if (t < Cc) {
        int coff = v1 - cnt;
        scoff[t] = coff;
        g_coff[t] = coff;
        g_counts[t] = cnt;
        int slot = v2 - flag;
        g_slot[t] = flag ? slot : -1;
        if (flag) g_kidx[slot] = t;
        float cf = (float)cnt;
        float denom = cf + amount[t];
        wv = (denom > 0.f) ? (cf / denom) : 0.f;
        g_wCV[t] = wv;
    }
    if (t == 0) g_Svar = wsum2[31];
    __syncthreads();
    g_list[scoff[l] + myrank] = t;
    // class-grouped row runs
    int rl = 0;
    if (t < Cc) {
        float coef2 = wv*(1.f - wv);
        rl = ((cnt >= 2) ? cnt : 0) + ((coef2 != 0.f) ? 1 : 0);
    }
    int f2 = (rl > 0) ? 1 : 0;
    __syncthreads();
    int v3 = rl, v4 = f2;
    scan2_1024(v3, v4, lane, w, wsum1, wsum2);
    if (t < Cc) {
        int rb = v3 - rl;
        g_rowbase[t] = rb;
        if (f2) {
            int j = v4 - f2;
            g_j2cls[j] = t;
            g_j2row0[j] = rb;
            g_j2len[j] = rl;
        }
    }
    if (t == 0) { g_Rvar = wsum1[31]; g_Jvar = wsum2[31]; }
}

// ---------------- fused per-class mean + centered-row fill (class-grouped slots) ----
__global__ void k_avefill(const float* __restrict__ f,
                          const float* __restrict__ ave_state) {
    int c = blockIdx.x, a = threadIdx.x;
    int cnt = g_counts[c], off = g_coff[c];
    float acc = 0.f;
    for (int i = 0; i < cnt; i++) acc += f[g_list[off+i]*Aa + a];
    float ave = acc / (float)(cnt > 0 ? cnt : 1);
    float w = g_wCV[c];
    int base = g_rowbase[c];
    bool sact = (cnt >= 2);
    if (sact) {
        float ac = w / (float)cnt;
        for (int i = 0; i < cnt; i++) {
            int n = g_list[off+i];
            int s = base + i;
            g_X[s*Aa + a] = f[n*Aa + a] - ave;
            if (a == 0) { g_rcls[s] = c; g_racoef[s] = ac; }
        }
    }
    float coef2 = w*(1.f - w);
    if (coef2 != 0.f) {
        int s2 = base + (sact ? cnt : 0);
        g_X[s2*Aa + a] = ave_state[c*Aa + a] - ave;
        if (a == 0) { g_rcls[s2] = c; g_racoef[s2] = coef2; }
    }
}

// P = X.W^T (64x64 tiles). Spare blocks: cov_state zero-scan + kgT transpose build.
__global__ void __launch_bounds__(256) k_P(const float* __restrict__ W,
                                           const float* __restrict__ cov,
                                           const float* __restrict__ kg,
                                           const int* __restrict__ headp) {
    int R = g_Rvar;
    int nkr64 = (R + 63) & ~63;
    int nby = nkr64 >> 6;
    int by = blockIdx.y, bx = blockIdx.x;
    __shared__ float Xs[64][65];
    __shared__ float Ws[64][65];
    int t = threadIdx.x;
    if (by >= nby) {
        int spare  = (by - nby)*gridDim.x + bx;
        int nspare = (gridDim.y - nby)*gridDim.x;
        {   // 1) cov_state zero-scan
            const float4* c4 = (const float4*)cov;
            int total = Cc*Aa*Aa/4;
            int found = 0;
            for (int i = spare*256 + t; i < total; i += nspare*256) {
                float4 v = c4[i];
                found |= (v.x != 0.f) | (v.y != 0.f) | (v.z != 0.f) | (v.w != 0.f);
            }
            if (found) atomicOr(&g_csflag, 1);
        }
        {   // 2) kgT build
            int S = g_Svar, hd = headp[0];
            float* tile = &Xs[0][0];            // reuse smem: 32x33 tile
            int tx = t & 31, ty8 = t >> 5;
            for (int tid = spare; tid < 1024; tid += nspare) {
                int s0 = (tid & 31) * 32;
                int j0 = (tid >> 5) * 32;
                #pragma unroll
                for (int i = 0; i < 4; i++) {
                    int row = ty8 + 8*i;
                    int s = s0 + row, j = j0 + tx;
                    float v = 0.f;
                    if (s < S && j < Cc) {
                        int k = g_kidx[s];
                        v = (k < hd) ? ((j == k) ? 1.f : 0.f) : kg[k*Cc + j];
                    }
                    tile[row*33 + tx] = v;
                }
                __syncthreads();
                #pragma unroll
                for (int i = 0; i < 4; i++) {
                    int row = ty8 + 8*i;
                    int j = j0 + row;
                    if (j < Cc) g_kgT[j*SP + s0 + tx] = tile[tx*33 + row];
                }
                __syncthreads();
            }
        }
        return;
    }
    int r0 = by*64, c0 = bx*64;
    for (int i = t; i < 64*64; i += 256) {
        int rr = i >> 6, kk = i & 63;
        int r = r0 + rr;
        Xs[rr][kk] = (r < R) ? g_X[r*Aa + kk] : 0.f;
        int c = c0 + rr;
        Ws[rr][kk] = (c < Cc) ? W[c*Aa + kk] : 0.f;
    }
    __syncthreads();
    int tx = t & 15, ty = t >> 4;
    float acc[4][4] = {};
    #pragma unroll 4
    for (int k = 0; k < 64; k++) {
        float xv[4], wv[4];
        #pragma unroll
        for (int i = 0; i < 4; i++) xv[i] = Xs[ty*4+i][k];
        #pragma unroll
        for (int j = 0; j < 4; j++) wv[j] = Ws[tx*4+j][k];
        #pragma unroll
        for (int i = 0; i < 4; i++)
            #pragma unroll
            for (int j = 0; j < 4; j++)
                acc[i][j] += xv[i]*wv[j];
    }
    #pragma unroll
    for (int i = 0; i < 4; i++) {
        int r = r0 + ty*4 + i;
        float4 v = (r < R) ? make_float4(acc[i][0], acc[i][1], acc[i][2], acc[i][3])
                           : make_float4(0.f, 0.f, 0.f, 0.f);
        *(float4*)&g_P[r*CP + c0 + tx*4] = v;
    }
}

// E[r,s] = beta*ac[r]*kgT[cl[r]][s]*P[r,kidx[s]]  (dead columns trimmed)
// Spare y-blocks build G[j,c] = sum_{r in run j} ac*P[r,c]^2
__global__ void __launch_bounds__(256) k_BE(const float* __restrict__ betap) {
    int R = g_Rvar;
    int nkr = (R + 15) & ~15;
    int nbyUsed = (nkr + 3) >> 2;
    int by = blockIdx.y;
    int t = threadIdx.x;
    if (by >= nbyUsed) {
        // ---- spare blocks: build G rows ----
        int spare  = (by - nbyUsed)*gridDim.x + blockIdx.x;
        int nspare = (gridDim.y - nbyUsed)*gridDim.x;
        int J = g_Jvar;
        int JP = (J + 15) & ~15;
        for (int j = spare; j < JP; j += nspare) {
            if (j < J) {
                int row0 = g_j2row0[j], len = g_j2len[j];
                for (int c = t*4; c < CP; c += 1024) {
                    float4 acc = make_float4(0.f, 0.f, 0.f, 0.f);
                    for (int i = 0; i < len; i++) {
                        int r = row0 + i;
                        float ac = g_racoef[r];
                        float4 p = *(const float4*)&g_P[r*CP + c];
                        acc.x += ac*p.x*p.x; acc.y += ac*p.y*p.y;
                        acc.z += ac*p.z*p.z; acc.w += ac*p.w*p.w;
                    }
                    *(float4*)&g_G[j*CP + c] = acc;
                }
            } else {
                for (int c = t*4; c < CP; c += 1024)
                    *(float4*)&g_G[j*CP + c] = make_float4(0.f, 0.f, 0.f, 0.f);
            }
        }
        return;
    }
    int S = g_Svar;
    int Smax64 = (S + 63) & ~63;
    if ((int)(blockIdx.x*256) >= Smax64) return;   // dead E columns
    int rbase = by*4;
    int s = blockIdx.x*256 + t;
    bool sv = (s < S);
    int k = sv ? g_kidx[s] : 0;
    float beta = betap[0];
    int   cl[4]; float ac[4];
    #pragma unroll
    for (int i = 0; i < 4; i++) {
        int r = rbase + i;
        cl[i] = (r < R) ? g_rcls[r] : 0;
        ac[i] = (r < R) ? g_racoef[r] : 0.f;
    }
    float kv[4], pv[4];
    #pragma unroll
    for (int i = 0; i < 4; i++) kv[i] = sv ? g_kgT[cl[i]*SP + s] : 0.f;
    #pragma unroll
    for (int i = 0; i < 4; i++) {
        int r = rbase + i;
        pv[i] = (sv && r < R) ? g_P[r*CP + k] : 0.f;
    }
    #pragma unroll
    for (int i = 0; i < 4; i++) {
        int r = rbase + i;
        float e = (sv && r < R) ? beta * ac[i] * kv[i] * pv[i] : 0.f;
        g_E[r*SP + s] = e;
    }
}

// F_partial[z] = (E^T X) K-chunk; z==0 also folds -alpha*out_new[k_s,:].
// Stored transposed: g_Fp[z][a][s].
__global__ void __launch_bounds__(256) k_F(const float* __restrict__ out_new,
                                           const float* __restrict__ alphap) {
    int s0 = blockIdx.x*64;
    if (s0 >= ((g_Svar + 63) & ~63)) return;       // dead s tiles
    int z = blockIdx.y;
    int t = threadIdx.x;
    int tx = t & 15, ty = t >> 4;
    int lr = t >> 4, lc = (t & 15)*4;
    int R = g_Rvar;
    int nkr = (R + 15) & ~15;
    int nt = nkr >> 4;
    int per = (nt + KSF - 1)/KSF;
    int ta = z*per, tb = ta + per; if (tb > nt) tb = nt;
    __shared__ __align__(16) float Es[16][64];
    __shared__ __align__(16) float Xs[16][64];
    float acc[4][4] = {};
    for (int tt = ta; tt < tb; tt++) {
        int r = tt*16 + lr;
        *(float4*)&Es[lr][lc] = *(const float4*)&g_E[r*SP + s0 + lc];
        *(float4*)&Xs[lr][lc] = *(const float4*)&g_X[r*Aa + lc];
        __syncthreads();
        #pragma unroll
        for (int u = 0; u < 16; u++) {
            float ev[4], xv[4];
            #pragma unroll
            for (int i = 0; i < 4; i++) ev[i] = Es[u][ty*4+i];
            #pragma unroll
            for (int j = 0; j < 4; j++) xv[j] = Xs[u][tx*4+j];
            #pragma unroll
            for (int i = 0; i < 4; i++)
                #pragma unroll
                for (int j = 0; j < 4; j++)
                    acc[i][j] += ev[i]*xv[j];
        }
        __syncthreads();
    }
    if (z == 0) {
        float alpha = alphap[0];
        #pragma unroll
        for (int i = 0; i < 4; i++) {
            int s = s0 + ty*4 + i;
            int k = (s < g_Svar) ? g_kidx[s] : 0;
            #pragma unroll
            for (int j = 0; j < 4; j++)
                acc[i][j] -= alpha * out_new[k*Aa + tx*4 + j];
        }
    }
    #pragma unroll
    for (int i = 0; i < 4; i++)
        #pragma unroll
        for (int j = 0; j < 4; j++)
            g_Fp[z*Aa*SP + (tx*4+j)*SP + (s0 + ty*4 + i)] = acc[i][j];
}

// k_QC: quad = kgT_grouped^T G (K=JP, z-split KS=2, f32x2);
//       z==0 also computes crossX = F_total * W^T (K=64).
__global__ void __launch_bounds__(256) k_QC(const float* __restrict__ W) {
    int s0 = blockIdx.y*64;
    if (s0 >= g_Svar) return;
    int c0 = blockIdx.x*64;
    int z = blockIdx.z;
    int t = threadIdx.x;
    int tx = t & 15, ty = t >> 4;
    int lr = t >> 4, lc = (t & 15)*4;
    __shared__ __align__(16) float As[16][64];
    __shared__ __align__(16) float Ms[16][64];
    unsigned long long qacc[8];
    #pragma unroll
    for (int i = 0; i < 8; i++) qacc[i] = 0ULL;
    {
        int J = g_Jvar;
        int JP = (J + 15) & ~15;
        int nt = JP >> 4;
        int per = (nt + KS - 1)/KS;
        int ta = z*per, tb = ta + per; if (tb > nt) tb = nt;
        if (ta < tb) {
            float4 rA, rM;
            {
                int j = ta*16 + lr;
                rA = (j < J) ? *(const float4*)&g_kgT[g_j2cls[j]*SP + s0 + lc]
                             : make_float4(0.f,0.f,0.f,0.f);
                rM = *(const float4*)&g_G[j*CP + c0 + lc];
            }
            for (int tt = ta; tt < tb; tt++) {
                *(float4*)&As[lr][lc] = rA;
                *(float4*)&Ms[lr][lc] = rM;
                __syncthreads();
                if (tt + 1 < tb) {
                    int j = (tt+1)*16 + lr;
                    rA = (j < J) ? *(const float4*)&g_kgT[g_j2cls[j]*SP + s0 + lc]
                                 : make_float4(0.f,0.f,0.f,0.f);
                    rM = *(const float4*)&g_G[j*CP + c0 + lc];
                }
                #pragma unroll
                for (int u = 0; u < 16; u++) {
                    float4 kv = *(float4*)&As[u][ty*4];
                    ulonglong2 gv = *(ulonglong2*)&Ms[u][tx*4];
                    unsigned long long k2[4];
                    k2[0] = pack2(kv.x, kv.x); k2[1] = pack2(kv.y, kv.y);
                    k2[2] = pack2(kv.z, kv.z); k2[3] = pack2(kv.w, kv.w);
                    #pragma unroll
                    for (int i = 0; i < 4; i++) {
                        fma2(qacc[i*2+0], k2[i], gv.x);
                        fma2(qacc[i*2+1], k2[i], gv.y);
                    }
                }
                __syncthreads();
            }
        }
    }
    int zoff = z*SP*CP;
    #pragma unroll
    for (int i = 0; i < 4; i++) {
        int s = s0 + ty*4 + i;
        unsigned long long* q = (unsigned long long*)&g_quad[zoff + s*CP + c0 + tx*4];
        q[0] = qacc[i*2+0]; q[1] = qacc[i*2+1];
    }
    if (z != 0) return;
    // ---- cross phase: crossX[s,c] = sum_a F[s,a] * W[c,a]  (K = 64) ----
    __shared__ float Wt[64][17];
    __syncthreads();
    float acc[4][4] = {};
    for (int a0 = 0; a0 < Aa; a0 += 16) {
        {
            int a = a0 + lr;
            float4 v = make_float4(0.f, 0.f, 0.f, 0.f);
            #pragma unroll
            for (int zz = 0; zz < KSF; zz++) {
                float4 f = *(const float4*)&g_Fp[zz*Aa*SP + a*SP + s0 + lc];
                v.x += f.x; v.y += f.y; v.z += f.z; v.w += f.w;
            }
            *(float4*)&As[lr][lc] = v;       // As[a_local][s_local]
        }
        {
            int cl = t >> 2;
            int aw = (t & 3)*4;
            int c = c0 + cl;
            float4 wv = (c < Cc) ? *(const float4*)&W[c*Aa + a0 + aw]
                                 : make_float4(0.f,0.f,0.f,0.f);
            Wt[cl][aw+0] = wv.x; Wt[cl][aw+1] = wv.y;
            Wt[cl][aw+2] = wv.z; Wt[cl][aw+3] = wv.w;
        }
        __syncthreads();
        #pragma unroll
        for (int u = 0; u < 16; u++) {
            float fv[4], wv2[4];
            #pragma unroll
            for (int i = 0; i < 4; i++) fv[i] = As[u][ty*4+i];
            #pragma unroll
            for (int j = 0; j < 4; j++) wv2[j] = Wt[tx*4+j][u];
            #pragma unroll
            for (int i = 0; i < 4; i++)
                #pragma unroll
                for (int j = 0; j < 4; j++)
                    acc[i][j] += fv[i]*wv2[j];
        }
        __syncthreads();
    }
    #pragma unroll
    for (int i = 0; i < 4; i++) {
        int s = s0 + ty*4 + i;
        *(float4*)&g_crossX[s*CP + c0 + tx*4] =
            make_float4(acc[i][0], acc[i][1], acc[i][2], acc[i][3]);
    }
}

// ---- guarded cov_state fallback (separate kernel: keeps k_QC's reg budget clean) ----
__global__ void __launch_bounds__(256) k_cs(const float* __restrict__ cov,
                                            const float* __restrict__ kg,
                                            const float* __restrict__ W,
                                            const float* __restrict__ betap,
                                            const int* __restrict__ headp) {
    if (!g_csflag) return;
    int s = blockIdx.x;
    if (s >= g_Svar) return;
    int k = g_kidx[s], hd = headp[0];
    float beta = betap[0];
    __shared__ float M[Aa*Aa];
    int t = threadIdx.x;
    for (int idx = t; idx < Aa*Aa; idx += 256) {
        float v;
        if (k < hd) v = (1.f - g_wCV[k]) * cov[k*4096 + idx];
        else {
            v = 0.f;
            for (int j = 0; j < Cc; j++)
                v += kg[k*Cc + j] * (1.f - g_wCV[j]) * cov[j*4096 + idx];
        }
        M[idx] = v;
    }
    __syncthreads();
    for (int c = t; c < Cc; c += 256) {
        float q = 0.f, cr = 0.f, cr2 = 0.f;
        for (int a = 0; a < Aa; a++) {
            float ta = 0.f, ua = 0.f;
            for (int b2 = 0; b2 < Aa; b2++) {
                ta += M[a*Aa + b2] * W[c*Aa + b2];
                ua += M[a*Aa + b2] * W[k*Aa + b2];
            }
            q   += W[c*Aa + a] * ta;
            cr  += W[k*Aa + a] * ta;
            cr2 += W[c*Aa + a] * ua;
        }
        g_quad[s*CP + c]   += q;
        g_crossX[s*CP + c] += beta * 0.5f * (cr + cr2);
    }
}

// ---- weighted CE (2 quad buffers + 1 cross) + fused final reduction ----
__global__ void __launch_bounds__(256) k_ce(const float* __restrict__ y_s,
                     const float* __restrict__ weights,
                     const int* __restrict__ labels,
                     const float* __restrict__ betap,
                     float* __restrict__ out) {
    int n = blockIdx.x, t = threadIdx.x;
    int k = labels[n];
    int s = g_slot[k];
    float hb = 0.5f * betap[0];
    __shared__ float red[256];
    __shared__ float sLk;
    __shared__ int slast;
    float L[4];
    float mx = -3.4e38f;
    #pragma unroll
    for (int i = 0; i < 4; i++) {
        int c = t + i*256;
        float v = -3.4e38f;
        if (c < Cc) {
            float q = g_quad[s*CP + c] + g_quad[SP*CP + s*CP + c];
            float x = g_crossX[s*CP + c];
            v = y_s[n*Cc + c] + hb*q - x;
            if (c == k) sLk = v;
        }
        L[i] = v;
        mx = fmaxf(mx, v);
    }
    red[t] = mx; __syncthreads();
    for (int o = 128; o > 0; o >>= 1) {
        if (t < o) red[t] = fmaxf(red[t], red[t+o]);
        __syncthreads();
    }
    float m = red[0]; __syncthreads();
    float se = 0.f;
    #pragma unroll
    for (int i = 0; i < 4; i++) {
        int c = t + i*256;
        if (c < Cc) se += expf(L[i] - m);
    }
    red[t] = se; __syncthreads();
    for (int o = 128; o > 0; o >>= 1) {
        if (t < o) red[t] += red[t+o];
        __syncthreads();
    }
    if (t == 0) {
        float lse = m + logf(red[0]);
        float w = weights[k];
        g_nllw[n] = w * (lse - sLk);
        g_wn[n] = w;
        __threadfence();
        unsigned v = atomicAdd(&g_done, 1u);
        slast = (v == (unsigned)(gridDim.x - 1)) ? 1 : 0;
    }
    __syncthreads();
    if (slast) {
        if (t == 0) { g_done = 0; __threadfence(); }
        __syncthreads();
        float a = g_nllw[t] + g_nllw[t+256] + g_nllw[t+512] + g_nllw[t+768];
        float b = g_wn[t]   + g_wn[t+256]   + g_wn[t+512]   + g_wn[t+768];
        red[t] = a; __syncthreads();
        for (int o = 128; o > 0; o >>= 1) {
            if (t < o) red[t] += red[t+o];
            __syncthreads();
        }
        a = red[0]; __syncthreads();
        red[t] = b; __syncthreads();
        for (int o = 128; o > 0; o >>= 1) {
            if (t < o) red[t] += red[t+o];
            __syncthreads();
        }
        if (t == 0) out[0] = a / red[0];
    }
}

extern "C" void kernel_launch(void* const* d_in, const int* in_sizes, int n_in,
                              void* d_out, int out_size) {
    const float* features  = (const float*)d_in[0];
    const float* y_s       = (const float*)d_in[1];
    const float* weights   = (const float*)d_in[2];
    const float* kg        = (const float*)d_in[3];
    const float* out_new   = (const float*)d_in[4];
    const float* fc_weight = (const float*)d_in[5];
    const float* alpha     = (const float*)d_in[6];
    const float* beta      = (const float*)d_in[7];
    const float* cov_state = (const float*)d_in[8];
    const float* ave_state = (const float*)d_in[9];
    const float* amount    = (const float*)d_in[10];
    const int*   labels    = (const int*)d_in[11];
    const int*   headp     = (const int*)d_in[12];
    float* out = (float*)d_out;

    k_stats<<<1, 1024>>>(labels, amount);
    k_avefill<<<Cc, Aa>>>(features, ave_state);
    {
        dim3 g(CP/64, RP/64 + 1);   // spare blocks: cov scan + kgT build
        k_P<<<g, 256>>>(fc_weight, cov_state, kg, headp);
    }
    {
        dim3 g(SP/256, RP/4);       // spare blocks: G build
        k_BE<<<g, 256>>>(beta);
    }
    {
        dim3 g(SP/64, KSF);
        k_F<<<g, 256>>>(out_new, alpha);
    }
    {
        dim3 g(CP/64, SP/64, KS);
        k_QC<<<g, 256>>>(fc_weight);
    }
    k_cs<<<SP, 256>>>(cov_state, kg, fc_weight, beta, headp);
    k_ce<<<Nn, 256>>>(y_s, weights, labels, beta, out);
}

// round 17
// speedup vs baseline: 1.3445x; 1.0470x over previous
#include <cuda_runtime.h>
#include <math.h>

#define Nn 1024
#define Cc 1000
#define Aa 64
#define SP 1024      /* padded S (distinct classes) */
#define RP 2112      /* padded rows */
#define CP 1024      /* padded C for row stride */
#define KS 2         /* K-split for quad phase */
#define KSF 4        /* K-split for F build */

static __device__ int   g_counts[Cc];
static __device__ int   g_coff[Cc];
static __device__ int   g_slot[Cc];
static __device__ int   g_kidx[SP];
static __device__ int   g_list[Nn];
static __device__ float g_wCV[Cc];
static __device__ int   g_Svar;
static __device__ int   g_Rvar;
static __device__ int   g_Jvar;
static __device__ int   g_rowbase[Cc];
static __device__ int   g_j2cls[SP];
static __device__ int   g_j2row0[SP];
static __device__ int   g_j2len[SP];
static __device__ int   g_rcls[RP];
static __device__ float g_racoef[RP];
static __device__ float g_X[RP*Aa];
static __device__ float g_P[RP*CP];
static __device__ float g_kgT[Cc*SP];     /* kgT[j][s] = delta or kg[kidx[s]][j] */
static __device__ float g_E[RP*SP];
static __device__ float g_G[SP*CP];       /* G[j][c] = sum_{r in class-run j} ac*P^2 */
static __device__ float g_Fp[KSF*Aa*SP];  /* partial F, transposed: [z][a][s] */
static __device__ float g_quad[KS*SP*CP];
static __device__ float g_crossX[SP*CP];
static __device__ float g_quadCS[SP*CP];  /* cov_state fallback terms (valid iff csflag) */
static __device__ float g_crossCS[SP*CP];
static __device__ float g_nllw[Nn];
static __device__ float g_wn[Nn];
static __device__ int   g_csflag;
static __device__ unsigned g_done = 0;

// packed f32x2 helpers (sm_100+ PTX)
__device__ __forceinline__ unsigned long long pack2(float lo, float hi) {
    unsigned long long d;
    asm("mov.b64 %0, {%1, %2};" : "=l"(d) : "f"(lo), "f"(hi));
    return d;
}
__device__ __forceinline__ void fma2(unsigned long long& acc, unsigned long long a, unsigned long long b) {
    asm("fma.rn.f32x2 %0, %1, %2, %0;" : "+l"(acc) : "l"(a), "l"(b));
}

// dual inclusive scan of 1024 (v1,v2) pairs via warp shuffles
__device__ __forceinline__ void scan2_1024(int& v1, int& v2, int lane, int w,
                                           int* wsum1, int* wsum2) {
    #pragma unroll
    for (int o = 1; o < 32; o <<= 1) {
        int x1 = __shfl_up_sync(0xffffffffu, v1, o);
        int x2 = __shfl_up_sync(0xffffffffu, v2, o);
        if (lane >= o) { v1 += x1; v2 += x2; }
    }
    if (lane == 31) { wsum1[w] = v1; wsum2[w] = v2; }
    __syncthreads();
    if (w == 0) {
        int s1 = wsum1[lane], s2 = wsum2[lane];
        #pragma unroll
        for (int o = 1; o < 32; o <<= 1) {
            int x1 = __shfl_up_sync(0xffffffffu, s1, o);
            int x2 = __shfl_up_sync(0xffffffffu, s2, o);
            if (lane >= o) { s1 += x1; s2 += x2; }
        }
        wsum1[lane] = s1; wsum2[lane] = s2;
    }
    __syncthreads();
    if (w > 0) { v1 += wsum1[w-1]; v2 += wsum2[w-1]; }
}

// ---------------- fused stats, 1 block ----------------
__global__ void __launch_bounds__(1024) k_stats(const int* __restrict__ labels,
                                                const float* __restrict__ amount) {
    __shared__ int   lab[1024];
    __shared__ int   scnt[1024];
    __shared__ int   scoff[1024];
    __shared__ int   wsum1[32], wsum2[32];
    int t = threadIdx.x, lane = t & 31, w = t >> 5;
    scnt[t] = 0;
    lab[t] = labels[t];
    if (t == 0) g_csflag = 0;
    __syncthreads();
    int l = lab[t];
    unsigned peers = __match_any_sync(0xffffffffu, l);
    int rin  = __popc(peers & ((1u << lane) - 1u));
    int ldr  = __ffs(peers) - 1;
    int cntw = __popc(peers);
    int base = 0;
    for (int ww = 0; ww < 32; ww++) {   // deterministic within-class ordering
        if (w == ww) {
            int old = 0;
            if (lane == ldr) old = atomicAdd(&scnt[l], cntw);
            base = __shfl_sync(0xffffffffu, old, ldr);
        }
        __syncthreads();
    }
    int myrank = base + rin;
    int cnt  = (t < Cc) ? scnt[t] : 0;
    int flag = (cnt > 0) ? 1 : 0;
    int v1 = cnt, v2 = flag;
    scan2_1024(v1, v2, lane, w, wsum1, wsum2);
    float wv = 0.f;
    if (t < Cc) {
        int coff = v1 - cnt;
        scoff[t] = coff;
        g_coff[t] = coff;
        g_counts[t] = cnt;
        int slot = v2 - flag;
        g_slot[t] = flag ? slot : -1;
        if (flag) g_kidx[slot] = t;
        float cf = (float)cnt;
        float denom = cf + amount[t];
        wv = (denom > 0.f) ? (cf / denom) : 0.f;
        g_wCV[t] = wv;
    }
    if (t == 0) g_Svar = wsum2[31];
    __syncthreads();
    g_list[scoff[l] + myrank] = t;
    // class-grouped row runs
    int rl = 0;
    if (t < Cc) {
        float coef2 = wv*(1.f - wv);
        rl = ((cnt >= 2) ? cnt : 0) + ((coef2 != 0.f) ? 1 : 0);
    }
    int f2 = (rl > 0) ? 1 : 0;
    __syncthreads();
    int v3 = rl, v4 = f2;
    scan2_1024(v3, v4, lane, w, wsum1, wsum2);
    if (t < Cc) {
        int rb = v3 - rl;
        g_rowbase[t] = rb;
        if (f2) {
            int j = v4 - f2;
            g_j2cls[j] = t;
            g_j2row0[j] = rb;
            g_j2len[j] = rl;
        }
    }
    if (t == 0) { g_Rvar = wsum1[31]; g_Jvar = wsum2[31]; }
}

// ---------------- fused per-class mean + centered-row fill (class-grouped slots) ----
__global__ void k_avefill(const float* __restrict__ f,
                          const float* __restrict__ ave_state) {
    int c = blockIdx.x, a = threadIdx.x;
    int cnt = g_counts[c], off = g_coff[c];
    float acc = 0.f;
    for (int i = 0; i < cnt; i++) acc += f[g_list[off+i]*Aa + a];
    float ave = acc / (float)(cnt > 0 ? cnt : 1);
    float w = g_wCV[c];
    int base = g_rowbase[c];
    bool sact = (cnt >= 2);
    if (sact) {
        float ac = w / (float)cnt;
        for (int i = 0; i < cnt; i++) {
            int n = g_list[off+i];
            int s = base + i;
            g_X[s*Aa + a] = f[n*Aa + a] - ave;
            if (a == 0) { g_rcls[s] = c; g_racoef[s] = ac; }
        }
    }
    float coef2 = w*(1.f - w);
    if (coef2 != 0.f) {
        int s2 = base + (sact ? cnt : 0);
        g_X[s2*Aa + a] = ave_state[c*Aa + a] - ave;
        if (a == 0) { g_rcls[s2] = c; g_racoef[s2] = coef2; }
    }
}

// P = X.W^T (64x64 tiles). Spare blocks: cov_state zero-scan + kgT transpose build.
__global__ void __launch_bounds__(256) k_P(const float* __restrict__ W,
                                           const float* __restrict__ cov,
                                           const float* __restrict__ kg,
                                           const int* __restrict__ headp) {
    int R = g_Rvar;
    int nkr64 = (R + 63) & ~63;
    int nby = nkr64 >> 6;
    int by = blockIdx.y, bx = blockIdx.x;
    __shared__ float Xs[64][65];
    __shared__ float Ws[64][65];
    int t = threadIdx.x;
    if (by >= nby) {
        int spare  = (by - nby)*gridDim.x + bx;
        int nspare = (gridDim.y - nby)*gridDim.x;
        {   // 1) cov_state zero-scan
            const float4* c4 = (const float4*)cov;
            int total = Cc*Aa*Aa/4;
            int found = 0;
            for (int i = spare*256 + t; i < total; i += nspare*256) {
                float4 v = c4[i];
                found |= (v.x != 0.f) | (v.y != 0.f) | (v.z != 0.f) | (v.w != 0.f);
            }
            if (found) atomicOr(&g_csflag, 1);
        }
        {   // 2) kgT build
            int S = g_Svar, hd = headp[0];
            float* tile = &Xs[0][0];            // reuse smem: 32x33 tile
            int tx = t & 31, ty8 = t >> 5;
            for (int tid = spare; tid < 1024; tid += nspare) {
                int s0 = (tid & 31) * 32;
                int j0 = (tid >> 5) * 32;
                #pragma unroll
                for (int i = 0; i < 4; i++) {
                    int row = ty8 + 8*i;
                    int s = s0 + row, j = j0 + tx;
                    float v = 0.f;
                    if (s < S && j < Cc) {
                        int k = g_kidx[s];
                        v = (k < hd) ? ((j == k) ? 1.f : 0.f) : kg[k*Cc + j];
                    }
                    tile[row*33 + tx] = v;
                }
                __syncthreads();
                #pragma unroll
                for (int i = 0; i < 4; i++) {
                    int row = ty8 + 8*i;
                    int j = j0 + row;
                    if (j < Cc) g_kgT[j*SP + s0 + tx] = tile[tx*33 + row];
                }
                __syncthreads();
            }
        }
        return;
    }
    int r0 = by*64, c0 = bx*64;
    for (int i = t; i < 64*64; i += 256) {
        int rr = i >> 6, kk = i & 63;
        int r = r0 + rr;
        Xs[rr][kk] = (r < R) ? g_X[r*Aa + kk] : 0.f;
        int c = c0 + rr;
        Ws[rr][kk] = (c < Cc) ? W[c*Aa + kk] : 0.f;
    }
    __syncthreads();
    int tx = t & 15, ty = t >> 4;
    float acc[4][4] = {};
    #pragma unroll 4
    for (int k = 0; k < 64; k++) {
        float xv[4], wv[4];
        #pragma unroll
        for (int i = 0; i < 4; i++) xv[i] = Xs[ty*4+i][k];
        #pragma unroll
        for (int j = 0; j < 4; j++) wv[j] = Ws[tx*4+j][k];
        #pragma unroll
        for (int i = 0; i < 4; i++)
            #pragma unroll
            for (int j = 0; j < 4; j++)
                acc[i][j] += xv[i]*wv[j];
    }
    #pragma unroll
    for (int i = 0; i < 4; i++) {
        int r = r0 + ty*4 + i;
        float4 v = (r < R) ? make_float4(acc[i][0], acc[i][1], acc[i][2], acc[i][3])
                           : make_float4(0.f, 0.f, 0.f, 0.f);
        *(float4*)&g_P[r*CP + c0 + tx*4] = v;
    }
}

// E[r,s] = beta*ac[r]*kgT[cl[r]][s]*P[r,kidx[s]]  (dead columns trimmed)
// Spare y-blocks build G[j,c] = sum_{r in run j} ac*P[r,c]^2
__global__ void __launch_bounds__(256) k_BE(const float* __restrict__ betap) {
    int R = g_Rvar;
    int nkr = (R + 15) & ~15;
    int nbyUsed = (nkr + 3) >> 2;
    int by = blockIdx.y;
    int t = threadIdx.x;
    if (by >= nbyUsed) {
        // ---- spare blocks: build G rows ----
        int spare  = (by - nbyUsed)*gridDim.x + blockIdx.x;
        int nspare = (gridDim.y - nbyUsed)*gridDim.x;
        int J = g_Jvar;
        int JP = (J + 15) & ~15;
        for (int j = spare; j < JP; j += nspare) {
            if (j < J) {
                int row0 = g_j2row0[j], len = g_j2len[j];
                for (int c = t*4; c < CP; c += 1024) {
                    float4 acc = make_float4(0.f, 0.f, 0.f, 0.f);
                    for (int i = 0; i < len; i++) {
                        int r = row0 + i;
                        float ac = g_racoef[r];
                        float4 p = *(const float4*)&g_P[r*CP + c];
                        acc.x += ac*p.x*p.x; acc.y += ac*p.y*p.y;
                        acc.z += ac*p.z*p.z; acc.w += ac*p.w*p.w;
                    }
                    *(float4*)&g_G[j*CP + c] = acc;
                }
            } else {
                for (int c = t*4; c < CP; c += 1024)
                    *(float4*)&g_G[j*CP + c] = make_float4(0.f, 0.f, 0.f, 0.f);
            }
        }
        return;
    }
    int S = g_Svar;
    int Smax64 = (S + 63) & ~63;
    if ((int)(blockIdx.x*256) >= Smax64) return;   // dead E columns
    int rbase = by*4;
    int s = blockIdx.x*256 + t;
    bool sv = (s < S);
    int k = sv ? g_kidx[s] : 0;
    float beta = betap[0];
    int   cl[4]; float ac[4];
    #pragma unroll
    for (int i = 0; i < 4; i++) {
        int r = rbase + i;
        cl[i] = (r < R) ? g_rcls[r] : 0;
        ac[i] = (r < R) ? g_racoef[r] : 0.f;
    }
    float kv[4], pv[4];
    #pragma unroll
    for (int i = 0; i < 4; i++) kv[i] = sv ? g_kgT[cl[i]*SP + s] : 0.f;
    #pragma unroll
    for (int i = 0; i < 4; i++) {
        int r = rbase + i;
        pv[i] = (sv && r < R) ? g_P[r*CP + k] : 0.f;
    }
    #pragma unroll
    for (int i = 0; i < 4; i++) {
        int r = rbase + i;
        float e = (sv && r < R) ? beta * ac[i] * kv[i] * pv[i] : 0.f;
        g_E[r*SP + s] = e;
    }
}

// F_partial[z] = (E^T X) K-chunk; z==0 also folds -alpha*out_new[k_s,:].
// Stored transposed: g_Fp[z][a][s].
// z==KSF plane: guarded cov_state fallback into CS buffers (no-op when csflag==0).
__global__ void __launch_bounds__(256) k_F(const float* __restrict__ out_new,
                                           const float* __restrict__ alphap,
                                           const float* __restrict__ cov,
                                           const float* __restrict__ kg,
                                           const float* __restrict__ W,
                                           const float* __restrict__ betap,
                                           const int* __restrict__ headp) {
    int z = blockIdx.y;
    int t = threadIdx.x;
    if (z == KSF) {
        // ---- cov_state fallback (cold path; isolated from hot GEMM kernels) ----
        if (!g_csflag) return;
        __shared__ float M[Aa*Aa];
        int S = g_Svar, hd = headp[0];
        float beta = betap[0];
        for (int s = blockIdx.x; s < S; s += gridDim.x) {
            int k = g_kidx[s];
            for (int idx = t; idx < Aa*Aa; idx += 256) {
                float v;
                if (k < hd) v = (1.f - g_wCV[k]) * cov[k*4096 + idx];
                else {
                    v = 0.f;
                    for (int j = 0; j < Cc; j++)
                        v += kg[k*Cc + j] * (1.f - g_wCV[j]) * cov[j*4096 + idx];
                }
                M[idx] = v;
            }
            __syncthreads();
            for (int c = t; c < Cc; c += 256) {
                float q = 0.f, cr = 0.f, cr2 = 0.f;
                for (int a = 0; a < Aa; a++) {
                    float ta = 0.f, ua = 0.f;
                    for (int b2 = 0; b2 < Aa; b2++) {
                        ta += M[a*Aa + b2] * W[c*Aa + b2];
                        ua += M[a*Aa + b2] * W[k*Aa + b2];
                    }
                    q   += W[c*Aa + a] * ta;
                    cr  += W[k*Aa + a] * ta;
                    cr2 += W[c*Aa + a] * ua;
                }
                g_quadCS[s*CP + c]  = q;
                g_crossCS[s*CP + c] = beta * 0.5f * (cr + cr2);
            }
            __syncthreads();
        }
        return;
    }
    int s0 = blockIdx.x*64;
    if (s0 >= ((g_Svar + 63) & ~63)) return;       // dead s tiles
    int tx = t & 15, ty = t >> 4;
    int lr = t >> 4, lc = (t & 15)*4;
    int R = g_Rvar;
    int nkr = (R + 15) & ~15;
    int nt = nkr >> 4;
    int per = (nt + KSF - 1)/KSF;
    int ta = z*per, tb = ta + per; if (tb > nt) tb = nt;
    __shared__ __align__(16) float Es[16][64];
    __shared__ __align__(16) float Xs[16][64];
    float acc[4][4] = {};
    for (int tt = ta; tt < tb; tt++) {
        int r = tt*16 + lr;
        *(float4*)&Es[lr][lc] = *(const float4*)&g_E[r*SP + s0 + lc];
        *(float4*)&Xs[lr][lc] = *(const float4*)&g_X[r*Aa + lc];
        __syncthreads();
        #pragma unroll
        for (int u = 0; u < 16; u++) {
            float ev[4], xv[4];
            #pragma unroll
            for (int i = 0; i < 4; i++) ev[i] = Es[u][ty*4+i];
            #pragma unroll
            for (int j = 0; j < 4; j++) xv[j] = Xs[u][tx*4+j];
            #pragma unroll
            for (int i = 0; i < 4; i++)
                #pragma unroll
                for (int j = 0; j < 4; j++)
                    acc[i][j] += ev[i]*xv[j];
        }
        __syncthreads();
    }
    if (z == 0) {
        float alpha = alphap[0];
        #pragma unroll
        for (int i = 0; i < 4; i++) {
            int s = s0 + ty*4 + i;
            int k = (s < g_Svar) ? g_kidx[s] : 0;
            #pragma unroll
            for (int j = 0; j < 4; j++)
                acc[i][j] -= alpha * out_new[k*Aa + tx*4 + j];
        }
    }
    #pragma unroll
    for (int i = 0; i < 4; i++)
        #pragma unroll
        for (int j = 0; j < 4; j++)
            g_Fp[z*Aa*SP + (tx*4+j)*SP + (s0 + ty*4 + i)] = acc[i][j];
}

// k_QC: quad = kgT_grouped^T G (K=JP, z-split KS=2, f32x2);
//       z==0 also computes crossX = F_total * W^T (K=64).
__global__ void __launch_bounds__(256) k_QC(const float* __restrict__ W) {
    int s0 = blockIdx.y*64;
    if (s0 >= g_Svar) return;
    int c0 = blockIdx.x*64;
    int z = blockIdx.z;
    int t = threadIdx.x;
    int tx = t & 15, ty = t >> 4;
    int lr = t >> 4, lc = (t & 15)*4;
    __shared__ __align__(16) float As[16][64];
    __shared__ __align__(16) float Ms[16][64];
    unsigned long long qacc[8];
    #pragma unroll
    for (int i = 0; i < 8; i++) qacc[i] = 0ULL;
    {
        int J = g_Jvar;
        int JP = (J + 15) & ~15;
        int nt = JP >> 4;
        int per = (nt + KS - 1)/KS;
        int ta = z*per, tb = ta + per; if (tb > nt) tb = nt;
        if (ta < tb) {
            float4 rA, rM;
            {
                int j = ta*16 + lr;
                rA = (j < J) ? *(const float4*)&g_kgT[g_j2cls[j]*SP + s0 + lc]
                             : make_float4(0.f,0.f,0.f,0.f);
                rM = *(const float4*)&g_G[j*CP + c0 + lc];
            }
            for (int tt = ta; tt < tb; tt++) {
                *(float4*)&As[lr][lc] = rA;
                *(float4*)&Ms[lr][lc] = rM;
                __syncthreads();
                if (tt + 1 < tb) {
                    int j = (tt+1)*16 + lr;
                    rA = (j < J) ? *(const float4*)&g_kgT[g_j2cls[j]*SP + s0 + lc]
                                 : make_float4(0.f,0.f,0.f,0.f);
                    rM = *(const float4*)&g_G[j*CP + c0 + lc];
                }
                #pragma unroll
                for (int u = 0; u < 16; u++) {
                    float4 kv = *(float4*)&As[u][ty*4];
                    ulonglong2 gv = *(ulonglong2*)&Ms[u][tx*4];
                    unsigned long long k2[4];
                    k2[0] = pack2(kv.x, kv.x); k2[1] = pack2(kv.y, kv.y);
                    k2[2] = pack2(kv.z, kv.z); k2[3] = pack2(kv.w, kv.w);
                    #pragma unroll
                    for (int i = 0; i < 4; i++) {
                        fma2(qacc[i*2+0], k2[i], gv.x);
                        fma2(qacc[i*2+1], k2[i], gv.y);
                    }
                }
                __syncthreads();
            }
        }
    }
    int zoff = z*SP*CP;
    #pragma unroll
    for (int i = 0; i < 4; i++) {
        int s = s0 + ty*4 + i;
        unsigned long long* q = (unsigned long long*)&g_quad[zoff + s*CP + c0 + tx*4];
        q[0] = qacc[i*2+0]; q[1] = qacc[i*2+1];
    }
    if (z != 0) return;
    // ---- cross phase: crossX[s,c] = sum_a F[s,a] * W[c,a]  (K = 64) ----
    __shared__ float Wt[64][17];
    __syncthreads();
    float acc[4][4] = {};
    for (int a0 = 0; a0 < Aa; a0 += 16) {
        {
            int a = a0 + lr;
            float4 v = make_float4(0.f, 0.f, 0.f, 0.f);
            #pragma unroll
            for (int zz = 0; zz < KSF; zz++) {
                float4 f = *(const float4*)&g_Fp[zz*Aa*SP + a*SP + s0 + lc];
                v.x += f.x; v.y += f.y; v.z += f.z; v.w += f.w;
            }
            *(float4*)&As[lr][lc] = v;       // As[a_local][s_local]
        }
        {
            int cl = t >> 2;
            int aw = (t & 3)*4;
            int c = c0 + cl;
            float4 wv = (c < Cc) ? *(const float4*)&W[c*Aa + a0 + aw]
                                 : make_float4(0.f,0.f,0.f,0.f);
            Wt[cl][aw+0] = wv.x; Wt[cl][aw+1] = wv.y;
            Wt[cl][aw+2] = wv.z; Wt[cl][aw+3] = wv.w;
        }
        __syncthreads();
        #pragma unroll
        for (int u = 0; u < 16; u++) {
            float fv[4], wv2[4];
            #pragma unroll
            for (int i = 0; i < 4; i++) fv[i] = As[u][ty*4+i];
            #pragma unroll
            for (int j = 0; j < 4; j++) wv2[j] = Wt[tx*4+j][u];
            #pragma unroll
            for (int i = 0; i < 4; i++)
                #pragma unroll
                for (int j = 0; j < 4; j++)
                    acc[i][j] += fv[i]*wv2[j];
        }
        __syncthreads();
    }
    #pragma unroll
    for (int i = 0; i < 4; i++) {
        int s = s0 + ty*4 + i;
        *(float4*)&g_crossX[s*CP + c0 + tx*4] =
            make_float4(acc[i][0], acc[i][1], acc[i][2], acc[i][3]);
    }
}

// ---- weighted CE (2 quad + cross [+ CS if flagged]) + fused final reduction ----
__global__ void __launch_bounds__(256) k_ce(const float* __restrict__ y_s,
                     const float* __restrict__ weights,
                     const int* __restrict__ labels,
                     const float* __restrict__ betap,
                     float* __restrict__ out) {
    int n = blockIdx.x, t = threadIdx.x;
    int k = labels[n];
    int s = g_slot[k];
    int csf = g_csflag;
    float hb = 0.5f * betap[0];
    __shared__ float red[256];
    __shared__ float sLk;
    __shared__ int slast;
    float L[4];
    float mx = -3.4e38f;
    #pragma unroll
    for (int i = 0; i < 4; i++) {
        int c = t + i*256;
        float v = -3.4e38f;
        if (c < Cc) {
            float q = g_quad[s*CP + c] + g_quad[SP*CP + s*CP + c];
            float x = g_crossX[s*CP + c];
            if (csf) { q += g_quadCS[s*CP + c]; x += g_crossCS[s*CP + c]; }
            v = y_s[n*Cc + c] + hb*q - x;
            if (c == k) sLk = v;
        }
        L[i] = v;
        mx = fmaxf(mx, v);
    }
    red[t] = mx; __syncthreads();
    for (int o = 128; o > 0; o >>= 1) {
        if (t < o) red[t] = fmaxf(red[t], red[t+o]);
        __syncthreads();
    }
    float m = red[0]; __syncthreads();
    float se = 0.f;
    #pragma unroll
    for (int i = 0; i < 4; i++) {
        int c = t + i*256;
        if (c < Cc) se += expf(L[i] - m);
    }
    red[t] = se; __syncthreads();
    for (int o = 128; o > 0; o >>= 1) {
        if (t < o) red[t] += red[t+o];
        __syncthreads();
    }
    if (t == 0) {
        float lse = m + logf(red[0]);
        float w = weights[k];
        g_nllw[n] = w * (lse - sLk);
        g_wn[n] = w;
        __threadfence();
        unsigned v = atomicAdd(&g_done, 1u);
        slast = (v == (unsigned)(gridDim.x - 1)) ? 1 : 0;
    }
    __syncthreads();
    if (slast) {
        if (t == 0) { g_done = 0; __threadfence(); }
        __syncthreads();
        float a = g_nllw[t] + g_nllw[t+256] + g_nllw[t+512] + g_nllw[t+768];
        float b = g_wn[t]   + g_wn[t+256]   + g_wn[t+512]   + g_wn[t+768];
        red[t] = a; __syncthreads();
        for (int o = 128; o > 0; o >>= 1) {
            if (t < o) red[t] += red[t+o];
            __syncthreads();
        }
        a = red[0]; __syncthreads();
        red[t] = b; __syncthreads();
        for (int o = 128; o > 0; o >>= 1) {
            if (t < o) red[t] += red[t+o];
            __syncthreads();
        }
        if (t == 0) out[0] = a / red[0];
    }
}

extern "C" void kernel_launch(void* const* d_in, const int* in_sizes, int n_in,
                              void* d_out, int out_size) {
    const float* features  = (const float*)d_in[0];
    const float* y_s       = (const float*)d_in[1];
    const float* weights   = (const float*)d_in[2];
    const float* kg        = (const float*)d_in[3];
    const float* out_new   = (const float*)d_in[4];
    const float* fc_weight = (const float*)d_in[5];
    const float* alpha     = (const float*)d_in[6];
    const float* beta      = (const float*)d_in[7];
    const float* cov_state = (const float*)d_in[8];
    const float* ave_state = (const float*)d_in[9];
    const float* amount    = (const float*)d_in[10];
    const int*   labels    = (const int*)d_in[11];
    const int*   headp     = (const int*)d_in[12];
    float* out = (float*)d_out;

    k_stats<<<1, 1024>>>(labels, amount);
    k_avefill<<<Cc, Aa>>>(features, ave_state);
    {
        dim3 g(CP/64, RP/64 + 1);   // spare blocks: cov scan + kgT build
        k_P<<<g, 256>>>(fc_weight, cov_state, kg, headp);
    }
    {
        dim3 g(SP/256, RP/4);       // spare blocks: G build
        k_BE<<<g, 256>>>(beta);
    }
    {
        dim3 g(SP/64, KSF + 1);     // z==KSF: cov_state fallback plane
        k_F<<<g, 256>>>(out_new, alpha, cov_state, kg, fc_weight, beta, headp);
    }
    {
        dim3 g(CP/64, SP/64, KS);
        k_QC<<<g, 256>>>(fc_weight);
    }
    k_ce<<<Nn, 256>>>(y_s, weights, labels, beta, out);
}